// round 12
// baseline (speedup 1.0000x reference)
#include <cuda_runtime.h>

#define DIMC 192
#define RJ   48          // DIM / RED
#define BB   4
#define HH   256
#define WW   256
#define HWSZ (HH * WW)   // 65536
#define EPSV 1e-5f
#define PSEGS 4
#define POOL_BLOCKS (DIMC * PSEGS)   // 768: one wave
#define CONV_BLOCKS (DIMC * 4)       // 768: (plane, quarter), one wave

// Scratch (no device allocation). Per-batch slices -> no cross-stage races.
__device__ float g_part[BB][DIMC * PSEGS];

__device__ __forceinline__ void pdl_trigger() {
    asm volatile("griddepcontrol.launch_dependents;" ::: "memory");
}
__device__ __forceinline__ void pdl_wait() {
    asm volatile("griddepcontrol.wait;" ::: "memory");
}

// ---------------------------------------------------------------------------
// Pool for batch b: 768 blocks x 256 thr, block = (channel, quarter-plane).
// Pure read stream. As PDL secondary it never waits (no data dep on convs).
// ---------------------------------------------------------------------------
__global__ __launch_bounds__(256) void pool_kernel(const float* __restrict__ x,
                                                   int b) {
    const int c   = blockIdx.x >> 2;
    const int seg = blockIdx.x & 3;
    const int tid = threadIdx.x;

    const float4* p = (const float4*)(x + ((size_t)(b * DIMC + c)) * HWSZ)
                      + seg * (HWSZ / 4 / PSEGS);
    float s = 0.f;
    #pragma unroll
    for (int i = 0; i < HWSZ / 4 / PSEGS / 256; i++) {   // 16 loads
        float4 v = p[tid + i * 256];
        s += (v.x + v.y) + (v.z + v.w);
    }
    #pragma unroll
    for (int o = 16; o > 0; o >>= 1) s += __shfl_down_sync(0xffffffffu, s, o);
    __shared__ float sm[8];
    const int lane = tid & 31, wrp = tid >> 5;
    if (lane == 0) sm[wrp] = s;
    __syncthreads();
    if (tid == 0) {
        g_part[b][c * PSEGS + seg] =
            sm[0]+sm[1]+sm[2]+sm[3]+sm[4]+sm[5]+sm[6]+sm[7];
    }
}

// ---------------------------------------------------------------------------
// Conv for batch b: 768 blocks x 256 thr, block = (plane c, quarter q).
// Entry: trigger PDL (release pool(b+1)), then wait on pool(b), then per-block
// weight-gen (tiny), then conv 64 rows. Reads L2-hot batch data; __stcs writes.
//   out(y,x) = w0*in(y-1,x-1)+w1*in(y-1,x)+w2*in(y-1,x+1)+w3*in(y,x-1)+bias
// ---------------------------------------------------------------------------
__global__ __launch_bounds__(256) void conv_kernel(
        const float* __restrict__ x,
        const float* __restrict__ w1,
        const float* __restrict__ gamma,
        const float* __restrict__ beta,
        const float* __restrict__ rmean,
        const float* __restrict__ rvar,
        const float* __restrict__ w2,
        const float* __restrict__ b2,
        const float* __restrict__ bias,
        float* __restrict__ out, int b) {
    pdl_trigger();                      // let pool(b+1) start overlapping now
    pdl_wait();                         // full dependency on pool(b)

    const int c = blockIdx.x >> 2;      // 0..191
    const int q = blockIdx.x & 3;       // quarter: rows [q*64, q*64+64)
    const int tid = threadIdx.x;
    const int lane = tid & 31;
    const int wrp  = tid >> 5;

    // ---- per-block weight generation for plane (b, c) ----
    __shared__ float t48[RJ];
    __shared__ float wts[4];
    if (tid < RJ) {
        const float* pw = w1 + tid * DIMC;
        const float* gp = g_part[b];
        float acc = 0.f;
        #pragma unroll 8
        for (int cc = 0; cc < DIMC; cc++) {
            float pooled = (gp[cc*4] + gp[cc*4+1] + gp[cc*4+2] + gp[cc*4+3])
                           * (1.0f / (float)HWSZ);
            acc = fmaf(pooled, pw[cc], acc);
        }
        acc = gamma[tid] * (acc - rmean[tid]) * rsqrtf(rvar[tid] + EPSV) + beta[tid];
        t48[tid] = fmaxf(acc, 0.f);
    }
    __syncthreads();
    if (tid < 4) {                       // mask 'A' keeps 3x3 taps 0..3
        const int o = c * 9 + tid;
        const float* pw2 = w2 + (size_t)o * RJ;
        float acc = b2[o];
        #pragma unroll
        for (int j = 0; j < RJ; j++) acc = fmaf(t48[j], pw2[j], acc);
        wts[tid] = acc;
    }
    __syncthreads();
    const float w0 = wts[0], w1t = wts[1], w2t = wts[2], w3 = wts[3];
    const float bs = bias[c];

    // ---- conv 64 rows: warp = row, 8 iterations ----
    const size_t plane = (size_t)(b * DIMC + c) * HWSZ;
    const float* base = x + plane;
    float* outp = out + plane;
    const int x0 = lane << 3;

    #pragma unroll 2
    for (int it = 0; it < 8; it++) {
        const int y = q * 64 + it * 8 + wrp;
        const float* rowc = base + y * WW;
        const float* rowm = rowc - WW;   // valid only when y>0 (warp-uniform)

        const float4 b0 = *(const float4*)(rowc + x0);
        const float4 b1 = *(const float4*)(rowc + x0 + 4);

        float4 a0, a1;
        if (y > 0) {
            a0 = *(const float4*)(rowm + x0);
            a1 = *(const float4*)(rowm + x0 + 4);
        } else {
            a0 = make_float4(0.f, 0.f, 0.f, 0.f); a1 = a0;
        }

        float am1 = __shfl_up_sync(0xffffffffu, a1.w, 1);
        float bm1 = __shfl_up_sync(0xffffffffu, b1.w, 1);
        float ap8 = __shfl_down_sync(0xffffffffu, a0.x, 1);
        if (lane == 0)  { am1 = 0.f; bm1 = 0.f; }
        if (lane == 31) { ap8 = 0.f; }

        const float A[10] = {am1, a0.x, a0.y, a0.z, a0.w,
                             a1.x, a1.y, a1.z, a1.w, ap8};
        const float Bv[8] = {bm1, b0.x, b0.y, b0.z, b0.w, b1.x, b1.y, b1.z};

        float o[8];
        #pragma unroll
        for (int i = 0; i < 8; i++)
            o[i] = fmaf(w0, A[i], fmaf(w1t, A[i+1],
                   fmaf(w2t, A[i+2], fmaf(w3, Bv[i], bs))));

        float* po = outp + y * WW + x0;
        __stcs((float4*)po,     make_float4(o[0], o[1], o[2], o[3]));
        __stcs((float4*)po + 1, make_float4(o[4], o[5], o[6], o[7]));
    }
}

// ---------------------------------------------------------------------------
extern "C" void kernel_launch(void* const* d_in, const int* in_sizes, int n_in,
                              void* d_out, int out_size) {
    const float* x     = (const float*)d_in[0];
    const float* w1    = (const float*)d_in[1];
    const float* gamma = (const float*)d_in[2];
    const float* beta  = (const float*)d_in[3];
    const float* rmean = (const float*)d_in[4];
    const float* rvar  = (const float*)d_in[5];
    const float* w2    = (const float*)d_in[6];
    const float* b2    = (const float*)d_in[7];
    const float* bias  = (const float*)d_in[8];
    float* out = (float*)d_out;

    // P0 plain (full serialization vs prior work). All later kernels carry the
    // PDL attribute: convs wait on their pool via griddepcontrol.wait; pools
    // don't wait (no data dependence) and start at the preceding conv's
    // entry trigger -> pool(b+1) DRAM reads overlap conv(b) DRAM writes.
    pool_kernel<<<POOL_BLOCKS, 256>>>(x, 0);

    cudaLaunchAttribute attr[1];
    attr[0].id = cudaLaunchAttributeProgrammaticStreamSerialization;
    attr[0].val.programmaticStreamSerializationAllowed = 1;

    cudaLaunchConfig_t cfg = {};
    cfg.blockDim = dim3(256, 1, 1);
    cfg.stream = 0;
    cfg.attrs = attr;
    cfg.numAttrs = 1;

    for (int b = 0; b < BB; b++) {
        cfg.gridDim = dim3(CONV_BLOCKS, 1, 1);
        cudaLaunchKernelEx(&cfg, conv_kernel,
                           x, w1, gamma, beta, rmean, rvar, w2, b2, bias,
                           out, b);
        if (b + 1 < BB) {
            cfg.gridDim = dim3(POOL_BLOCKS, 1, 1);
            cudaLaunchKernelEx(&cfg, pool_kernel, x, b + 1);
        }
    }
}

// round 13
// speedup vs baseline: 2.1921x; 2.1921x over previous
#include <cuda_runtime.h>

#define DIMC 192
#define RJ   48          // DIM / RED
#define BB   4
#define HH   256
#define WW   256
#define HWSZ (HH * WW)   // 65536
#define EPSV 1e-5f
#define NPLANES (BB * DIMC)       // 768

// Scratch (no device allocation allowed).
__device__ float        g_pooled[NPLANES];   // per-plane means
__device__ float        g_wt[NPLANES * 4];   // 4 surviving masked taps per (b,c)
__device__ unsigned int g_cnt[BB] = {0, 0, 0, 0};  // per-batch arrival counters (wrap)

// ---------------------------------------------------------------------------
// Kernel 1: pool + fused per-batch weight-gen.
// One block per plane (768 blocks, proven 6.2 TB/s). The last block to finish
// within each batch runs that batch's MLP tail (counter wraps -> replay-safe).
// ---------------------------------------------------------------------------
__global__ __launch_bounds__(256) void pool_wgen_kernel(
        const float* __restrict__ x,
        const float* __restrict__ w1,
        const float* __restrict__ gamma,
        const float* __restrict__ beta,
        const float* __restrict__ rmean,
        const float* __restrict__ rvar,
        const float* __restrict__ w2,
        const float* __restrict__ b2) {
    const int bc  = blockIdx.x;                      // 0..767
    const int b   = bc / DIMC;
    const int tid = threadIdx.x;
    const int lane = tid & 31;
    const int wrp  = tid >> 5;

    const float4* p = (const float4*)(x + (size_t)bc * HWSZ);
    float s = 0.f;
    for (int i = tid; i < HWSZ / 4; i += 256) {
        float4 v = p[i];
        s += (v.x + v.y) + (v.z + v.w);
    }
    #pragma unroll
    for (int o = 16; o > 0; o >>= 1) s += __shfl_down_sync(0xffffffffu, s, o);
    __shared__ float sm[8];
    if (lane == 0) sm[wrp] = s;
    __syncthreads();
    __shared__ bool is_last;
    if (tid == 0) {
        float t = sm[0]+sm[1]+sm[2]+sm[3]+sm[4]+sm[5]+sm[6]+sm[7];
        g_pooled[bc] = t * (1.0f / (float)HWSZ);
        __threadfence();
        unsigned int old = atomicInc(&g_cnt[b], DIMC - 1);   // wraps 191 -> 0
        is_last = (old == DIMC - 1);
    }
    __syncthreads();
    if (!is_last) return;

    // ---- weight-gen tail for batch b (one block, ~sub-microsecond) ----
    __shared__ float t48[RJ];
    if (tid < RJ) {
        const float* pw = w1 + tid * DIMC;
        const float* pp = g_pooled + b * DIMC;
        float acc = 0.f;
        #pragma unroll 8
        for (int cc = 0; cc < DIMC; cc++)
            acc = fmaf(__ldcg(pp + cc), pw[cc], acc);
        acc = gamma[tid] * (acc - rmean[tid]) * rsqrtf(rvar[tid] + EPSV) + beta[tid];
        t48[tid] = fmaxf(acc, 0.f);
    }
    __syncthreads();
    // 768 masked taps (mask 'A' keeps 3x3 positions 0..3), 3 per thread.
    #pragma unroll
    for (int i = 0; i < 3; i++) {
        const int idx = tid + i * 256;       // 0..767
        const int cc = idx >> 2;
        const int k  = idx & 3;
        const int o  = cc * 9 + k;
        const float* pw2 = w2 + (size_t)o * RJ;
        float acc = b2[o];
        #pragma unroll
        for (int j = 0; j < RJ; j++) acc = fmaf(t48[j], pw2[j], acc);
        g_wt[(b * DIMC + cc) * 4 + k] = acc;
    }
}

// ---------------------------------------------------------------------------
// Kernel 2: masked depthwise conv (R7-winning form, 512 thr = 16 rows/block).
//   out(y,x) = w0*in(y-1,x-1)+w1*in(y-1,x)+w2*in(y-1,x+1)+w3*in(y,x-1)+bias
// One warp = one full row; 4 LDG.128 + 2 STG.128/thread; shuffle halos.
// Grid (16 rowtiles, 768 planes reversed): rowtile-fastest, so the first
// wave consumes the most-recently-pooled planes (L2 residue).
// ---------------------------------------------------------------------------
__global__ __launch_bounds__(512) void conv_kernel(const float* __restrict__ x,
                                                   const float* __restrict__ bias,
                                                   float* __restrict__ out) {
    const int bc = (NPLANES - 1) - blockIdx.y;      // reversed: 767..0
    const int c  = bc % DIMC;
    const float4 wv = *(const float4*)(g_wt + bc * 4);
    const float w0 = wv.x, w1 = wv.y, w2 = wv.z, w3 = wv.w;
    const float bs = bias[c];

    const int lane = threadIdx.x & 31;
    const int y    = blockIdx.x * 16 + (threadIdx.x >> 5);
    const int x0   = lane << 3;                     // 8 floats per thread

    const float* base = x + (size_t)bc * HWSZ;
    const float* rowc = base + y * WW;
    const float* rowm = rowc - WW;                  // deref'd only when y>0 (warp-uniform)

    const float4 b0 = __ldcs((const float4*)(rowc + x0));
    const float4 b1 = __ldcs((const float4*)(rowc + x0 + 4));

    float4 a0, a1;
    if (y > 0) {                                     // warp-uniform
        a0 = __ldcs((const float4*)(rowm + x0));
        a1 = __ldcs((const float4*)(rowm + x0 + 4));
    } else {
        a0 = make_float4(0.f, 0.f, 0.f, 0.f); a1 = a0;
    }

    float am1 = __shfl_up_sync(0xffffffffu, a1.w, 1);
    float bm1 = __shfl_up_sync(0xffffffffu, b1.w, 1);
    float ap8 = __shfl_down_sync(0xffffffffu, a0.x, 1);
    if (lane == 0)  { am1 = 0.f; bm1 = 0.f; }
    if (lane == 31) { ap8 = 0.f; }

    const float A[10] = {am1, a0.x, a0.y, a0.z, a0.w, a1.x, a1.y, a1.z, a1.w, ap8};
    const float Bv[8] = {bm1, b0.x, b0.y, b0.z, b0.w, b1.x, b1.y, b1.z};

    float o[8];
    #pragma unroll
    for (int i = 0; i < 8; i++)
        o[i] = fmaf(w0, A[i], fmaf(w1, A[i+1], fmaf(w2, A[i+2], fmaf(w3, Bv[i], bs))));

    float* po = out + (size_t)bc * HWSZ + y * WW + x0;
    __stcs((float4*)po,     make_float4(o[0], o[1], o[2], o[3]));
    __stcs((float4*)po + 1, make_float4(o[4], o[5], o[6], o[7]));
}

// ---------------------------------------------------------------------------
extern "C" void kernel_launch(void* const* d_in, const int* in_sizes, int n_in,
                              void* d_out, int out_size) {
    const float* x     = (const float*)d_in[0];
    const float* w1    = (const float*)d_in[1];
    const float* gamma = (const float*)d_in[2];
    const float* beta  = (const float*)d_in[3];
    const float* rmean = (const float*)d_in[4];
    const float* rvar  = (const float*)d_in[5];
    const float* w2    = (const float*)d_in[6];
    const float* b2    = (const float*)d_in[7];
    const float* bias  = (const float*)d_in[8];
    float* out = (float*)d_out;

    pool_wgen_kernel<<<NPLANES, 256>>>(x, w1, gamma, beta, rmean, rvar, w2, b2);

    dim3 grid(HH / 16, NPLANES);                    // (16, 768), y = reversed plane
    conv_kernel<<<grid, 512>>>(x, bias, out);
}

// round 14
// speedup vs baseline: 2.2384x; 1.0211x over previous
#include <cuda_runtime.h>

#define DIMC 192
#define RJ   48          // DIM / RED
#define BB   4
#define HH   256
#define WW   256
#define HWSZ (HH * WW)   // 65536
#define EPSV 1e-5f
#define NPLANES (BB * DIMC)       // 768

// Scratch (no device allocation allowed).
__device__ float g_pooled[NPLANES];      // per-plane means
__device__ float g_wt[NPLANES * 4];      // 4 surviving masked taps per (b,c)

// ---------------------------------------------------------------------------
// Kernel 1: global average pool per (b,c). One block per channel plane.
// R7-proven form: no atomics, no fences — 6.2 TB/s.
// ---------------------------------------------------------------------------
__global__ void pool_kernel(const float* __restrict__ x) {
    const int bc = blockIdx.x;                       // 0..767
    const float4* p = (const float4*)(x + (size_t)bc * HWSZ);
    const int n4 = HWSZ / 4;                         // 16384
    float s = 0.f;
    for (int i = threadIdx.x; i < n4; i += blockDim.x) {
        float4 v = p[i];
        s += (v.x + v.y) + (v.z + v.w);
    }
    #pragma unroll
    for (int o = 16; o > 0; o >>= 1) s += __shfl_down_sync(0xffffffffu, s, o);
    __shared__ float sm[32];
    const int lane = threadIdx.x & 31;
    const int wrp  = threadIdx.x >> 5;
    if (lane == 0) sm[wrp] = s;
    __syncthreads();
    if (wrp == 0) {
        s = (lane < (int)(blockDim.x >> 5)) ? sm[lane] : 0.f;
        #pragma unroll
        for (int o = 16; o > 0; o >>= 1) s += __shfl_down_sync(0xffffffffu, s, o);
        if (lane == 0) g_pooled[bc] = s * (1.0f / (float)HWSZ);
    }
}

// ---------------------------------------------------------------------------
// Kernel 2: dynamic weight generation (tiny, R7-proven).
// ---------------------------------------------------------------------------
__global__ void wgen_kernel(const float* __restrict__ w1,
                            const float* __restrict__ gamma,
                            const float* __restrict__ beta,
                            const float* __restrict__ rmean,
                            const float* __restrict__ rvar,
                            const float* __restrict__ w2,
                            const float* __restrict__ b2) {
    const int b   = blockIdx.x;
    const int tid = threadIdx.x;
    __shared__ float t[RJ];

    if (tid < RJ) {
        const float* pw = w1 + tid * DIMC;
        const float* pp = g_pooled + b * DIMC;
        float acc = 0.f;
        #pragma unroll 8
        for (int c = 0; c < DIMC; c++) acc = fmaf(pp[c], pw[c], acc);
        acc = gamma[tid] * (acc - rmean[tid]) * rsqrtf(rvar[tid] + EPSV) + beta[tid];
        t[tid] = fmaxf(acc, 0.f);
    }
    __syncthreads();

    // tid -> (channel c, tap k). Mask 'A' keeps 3x3 positions 0..3.
    const int c = tid >> 2;
    const int k = tid & 3;
    const int o = c * 9 + k;
    const float* pw2 = w2 + (size_t)o * RJ;
    float acc = b2[o];
    #pragma unroll
    for (int j = 0; j < RJ; j++) acc = fmaf(t[j], pw2[j], acc);
    g_wt[(b * DIMC + c) * 4 + k] = acc;
}

// ---------------------------------------------------------------------------
// Kernel 3: masked depthwise conv — R13-measured 57.7us @ 75.8% DRAM.
//   out(y,x) = w0*in(y-1,x-1)+w1*in(y-1,x)+w2*in(y-1,x+1)+w3*in(y,x-1)+bias
// 512 threads = 16 rows/block; warp = full row; 4 LDG.128 + 2 STG.128/thread;
// shuffle halos; grid (16, 768) with planes reversed (L2 residue order).
// ---------------------------------------------------------------------------
__global__ __launch_bounds__(512) void conv_kernel(const float* __restrict__ x,
                                                   const float* __restrict__ bias,
                                                   float* __restrict__ out) {
    const int bc = (NPLANES - 1) - blockIdx.y;      // reversed: 767..0
    const int c  = bc % DIMC;
    const float4 wv = *(const float4*)(g_wt + bc * 4);
    const float w0 = wv.x, w1 = wv.y, w2 = wv.z, w3 = wv.w;
    const float bs = bias[c];

    const int lane = threadIdx.x & 31;
    const int y    = blockIdx.x * 16 + (threadIdx.x >> 5);
    const int x0   = lane << 3;                     // 8 floats per thread

    const float* base = x + (size_t)bc * HWSZ;
    const float* rowc = base + y * WW;
    const float* rowm = rowc - WW;                  // deref'd only when y>0 (warp-uniform)

    const float4 b0 = __ldcs((const float4*)(rowc + x0));
    const float4 b1 = __ldcs((const float4*)(rowc + x0 + 4));

    float4 a0, a1;
    if (y > 0) {                                     // warp-uniform
        a0 = __ldcs((const float4*)(rowm + x0));
        a1 = __ldcs((const float4*)(rowm + x0 + 4));
    } else {
        a0 = make_float4(0.f, 0.f, 0.f, 0.f); a1 = a0;
    }

    float am1 = __shfl_up_sync(0xffffffffu, a1.w, 1);
    float bm1 = __shfl_up_sync(0xffffffffu, b1.w, 1);
    float ap8 = __shfl_down_sync(0xffffffffu, a0.x, 1);
    if (lane == 0)  { am1 = 0.f; bm1 = 0.f; }
    if (lane == 31) { ap8 = 0.f; }

    const float A[10] = {am1, a0.x, a0.y, a0.z, a0.w, a1.x, a1.y, a1.z, a1.w, ap8};
    const float Bv[8] = {bm1, b0.x, b0.y, b0.z, b0.w, b1.x, b1.y, b1.z};

    float o[8];
    #pragma unroll
    for (int i = 0; i < 8; i++)
        o[i] = fmaf(w0, A[i], fmaf(w1, A[i+1], fmaf(w2, A[i+2], fmaf(w3, Bv[i], bs))));

    float* po = out + (size_t)bc * HWSZ + y * WW + x0;
    __stcs((float4*)po,     make_float4(o[0], o[1], o[2], o[3]));
    __stcs((float4*)po + 1, make_float4(o[4], o[5], o[6], o[7]));
}

// ---------------------------------------------------------------------------
extern "C" void kernel_launch(void* const* d_in, const int* in_sizes, int n_in,
                              void* d_out, int out_size) {
    const float* x     = (const float*)d_in[0];
    const float* w1    = (const float*)d_in[1];
    const float* gamma = (const float*)d_in[2];
    const float* beta  = (const float*)d_in[3];
    const float* rmean = (const float*)d_in[4];
    const float* rvar  = (const float*)d_in[5];
    const float* w2    = (const float*)d_in[6];
    const float* b2    = (const float*)d_in[7];
    const float* bias  = (const float*)d_in[8];
    float* out = (float*)d_out;

    pool_kernel<<<NPLANES, 256>>>(x);
    wgen_kernel<<<BB, DIMC * 4>>>(w1, gamma, beta, rmean, rvar, w2, b2);

    dim3 grid(HH / 16, NPLANES);                    // (16, 768), y = reversed plane
    conv_kernel<<<grid, 512>>>(x, bias, out);
}